// round 2
// baseline (speedup 1.0000x reference)
#include <cuda_runtime.h>
#include <cuda_bf16.h>

// Problem: x [64,224,224,32] f32; W_cls [32,4]; b_cls [4].
// out[b] = rot90(x[b], k[b]) with k[b] = argmax(mean_hw(x[b]) @ W + b).
//
// Stage 1: deterministic per-(batch,chunk) channel sums  (reads 411 MB)  ~62us (at roofline)
// Stage 2: mean -> logits -> argmax per batch            (tiny)
// Stage 3: smem-TILED rotation: 16x16-pixel tiles, 2KB-coalesced on both
//          the read and the write side for all k.        (822 MB)

#define BATCH 64
#define HW    224
#define PIX   (HW * HW)        // 50176 pixels per image
#define CH    32               // channels; one pixel = 128 B = 8 float4
#define NCHUNK 49              // 49 * 1024 = 50176
#define CHUNK_PIX 1024
#define TS    16               // tile side in pixels; 224 = 14*16
#define NT    14               // tiles per dimension

// Scratch (no device allocation allowed) — fully overwritten every call.
__device__ float4 g_partial[BATCH * NCHUNK * 8];   // per-chunk channel sums
__device__ int    g_k[BATCH];

// ---------------- Stage 1: chunked channel-sum reduction -------------------
__global__ void __launch_bounds__(256) stage1_reduce(const float4* __restrict__ x) {
    int blk   = blockIdx.x;
    int b     = blk / NCHUNK;
    int chunk = blk - b * NCHUNK;
    int t     = threadIdx.x;
    int lane  = t & 31;
    int warp  = t >> 5;
    int q     = t & 7;                 // float4 slot within pixel

    unsigned base = ((unsigned)b * PIX + (unsigned)chunk * CHUNK_PIX) * 8u;

    float4 s = make_float4(0.f, 0.f, 0.f, 0.f);
#pragma unroll 4
    for (int it = 0; it < 32; ++it) {
        unsigned pix = (unsigned)(it * 32 + (t >> 3));
        float4 v = __ldg(&x[base + pix * 8u + q]);
        s.x += v.x; s.y += v.y; s.z += v.z; s.w += v.w;
    }
#pragma unroll
    for (int off = 8; off <= 16; off <<= 1) {
        s.x += __shfl_xor_sync(0xffffffffu, s.x, off);
        s.y += __shfl_xor_sync(0xffffffffu, s.y, off);
        s.z += __shfl_xor_sync(0xffffffffu, s.z, off);
        s.w += __shfl_xor_sync(0xffffffffu, s.w, off);
    }

    __shared__ float4 sm[8][8];        // [warp][q]
    if (lane < 8) sm[warp][lane] = s;
    __syncthreads();

    if (t < 8) {
        float4 acc = sm[0][t];
#pragma unroll
        for (int w = 1; w < 8; ++w) {
            float4 v = sm[w][t];
            acc.x += v.x; acc.y += v.y; acc.z += v.z; acc.w += v.w;
        }
        g_partial[(b * NCHUNK + chunk) * 8 + t] = acc;
    }
}

// ---------------- Stage 2: mean -> logits -> argmax ------------------------
__global__ void stage2_argmax(const float* __restrict__ W_cls,
                              const float* __restrict__ b_cls) {
    int b = blockIdx.x;
    int c = threadIdx.x;               // 0..31
    int q = c >> 2;
    int r = c & 3;

    float s = 0.f;
    for (int ch = 0; ch < NCHUNK; ++ch) {
        float4 v = g_partial[(b * NCHUNK + ch) * 8 + q];
        s += (r == 0) ? v.x : (r == 1) ? v.y : (r == 2) ? v.z : v.w;
    }
    __shared__ float mean[CH];
    mean[c] = s * (1.0f / (float)PIX);
    __syncthreads();

    if (c == 0) {
        float best = -3.402823466e38f;
        int bi = 0;
#pragma unroll
        for (int o = 0; o < 4; ++o) {
            float l = b_cls[o];
#pragma unroll
            for (int cc = 0; cc < CH; ++cc)
                l += mean[cc] * W_cls[cc * 4 + o];
            if (l > best) { best = l; bi = o; }   // first-max tie-break (jnp.argmax)
        }
        g_k[b] = bi;
    }
}

// ---------------- Stage 3: tiled rotation ----------------------------------
// Block = 256 threads handles one 16x16-pixel output tile (32 KB smem).
// Source of an output tile under rot90^k is also a 16x16 tile:
//   k=0: (si0,sj0)=(i0,j0)          lsi=li,    lsj=lj
//   k=1: (j0, 208-i0)               lsi=lj,    lsj=15-li
//   k=2: (208-i0, 208-j0)           lsi=15-li, lsj=15-lj
//   k=3: (208-j0, i0)               lsi=15-lj, lsj=li
// Both global phases are 2KB-contiguous per tile row. Smem is conflict-free:
// each 8-thread LDS/STS subphase touches one whole 128B pixel.
__global__ void __launch_bounds__(256) stage3_rotate_tiled(const float4* __restrict__ x,
                                                           float4* __restrict__ out) {
    __shared__ float4 tile[TS * TS * 8];     // 32 KB

    unsigned blk = blockIdx.x;
    unsigned tj  = blk % NT;
    unsigned tmp = blk / NT;
    unsigned ti  = tmp % NT;
    unsigned b   = tmp / NT;

    int k  = g_k[b];
    int i0 = (int)ti * TS, j0 = (int)tj * TS;
    int si0, sj0;
    switch (k) {
        case 0:  si0 = i0;            sj0 = j0;            break;
        case 1:  si0 = j0;            sj0 = HW - TS - i0;  break;
        case 2:  si0 = HW - TS - i0;  sj0 = HW - TS - j0;  break;
        default: si0 = HW - TS - j0;  sj0 = i0;            break;
    }

    const float4* src_base = x   + (unsigned)b * PIX * 8u;
    float4*       out_base = out + (unsigned)b * PIX * 8u;

    int t = threadIdx.x;
    int q = t & 7;

    // Load source tile, row-coalesced (2KB contiguous per tile row).
#pragma unroll
    for (int it = 0; it < 8; ++it) {
        int l   = it * 256 + t;
        int pix = l >> 3;              // 0..255
        int r   = pix >> 4;            // source tile row
        int cc  = pix & 15;            // source tile col
        tile[pix * 8 + q] = __ldg(&src_base[(unsigned)((si0 + r) * HW + (sj0 + cc)) * 8u + q]);
    }
    __syncthreads();

    // Write output tile, row-coalesced; transpose/reverse happens in smem.
#pragma unroll
    for (int it = 0; it < 8; ++it) {
        int l   = it * 256 + t;
        int pix = l >> 3;
        int li  = pix >> 4;
        int lj  = pix & 15;
        int lsi, lsj;
        switch (k) {
            case 0:  lsi = li;          lsj = lj;          break;
            case 1:  lsi = lj;          lsj = TS - 1 - li; break;
            case 2:  lsi = TS - 1 - li; lsj = TS - 1 - lj; break;
            default: lsi = TS - 1 - lj; lsj = li;          break;
        }
        out_base[(unsigned)((i0 + li) * HW + (j0 + lj)) * 8u + q] =
            tile[(lsi * TS + lsj) * 8 + q];
    }
}

extern "C" void kernel_launch(void* const* d_in, const int* in_sizes, int n_in,
                              void* d_out, int out_size) {
    const float4* x     = (const float4*)d_in[0];
    const float*  W_cls = (const float*)d_in[1];
    const float*  b_cls = (const float*)d_in[2];
    float4*       out   = (float4*)d_out;

    stage1_reduce<<<BATCH * NCHUNK, 256>>>(x);
    stage2_argmax<<<BATCH, 32>>>(W_cls, b_cls);
    stage3_rotate_tiled<<<BATCH * NT * NT, 256>>>(x, out);   // 12544 blocks
}

// round 3
// speedup vs baseline: 1.0598x; 1.0598x over previous
#include <cuda_runtime.h>
#include <cuda_bf16.h>

// Problem: x [64,224,224,32] f32; W_cls [32,4]; b_cls [4].
// out[b] = rot90(x[b], k[b]) with k[b] = argmax(mean_hw(x[b]) @ W + b).
//
// Single persistent kernel with an atomic work queue:
//   tasks [0, 3136):    reduction chunks (1024 px each), batch-major.
//                       Last finisher per batch computes k[b], releases flag.
//   tasks [3136, 6272): rotation slices (1024 px each), batch-major,
//                       spin-wait on flag[b] then gather-rotate.
// Overlaps the pure-read reduction stream with the read+write rotation
// stream so combined DRAM traffic stays saturated.

#define BATCH 64
#define HW    224
#define PIX   (HW * HW)        // 50176
#define CH    32
#define NCHUNK 49              // 49 * 1024 = 50176
#define RED_TASKS   (BATCH * NCHUNK)          // 3136
#define ROT_TASKS   (BATCH * NCHUNK)          // 3136
#define TOTAL_TASKS (RED_TASKS + ROT_TASKS)   // 6272
#define GRID_BLOCKS (148 * 8)                 // persistent-ish; queue-driven

// Scratch (no device allocation allowed) — reset by init kernel each call.
__device__ float4   g_partial[BATCH * NCHUNK * 8];
__device__ int      g_k[BATCH];
__device__ unsigned g_ctr;
__device__ int      g_done[BATCH];
__device__ int      g_flag[BATCH];

__global__ void init_kernel() {
    int t = threadIdx.x;
    if (t == 0) g_ctr = 0u;
    if (t < BATCH) { g_done[t] = 0; g_flag[t] = 0; }
}

__global__ void __launch_bounds__(256, 8) fused_kernel(const float4* __restrict__ x,
                                                       const float*  __restrict__ W_cls,
                                                       const float*  __restrict__ b_cls,
                                                       float4*       __restrict__ out) {
    __shared__ float4 sm[8][8];
    __shared__ float  meanv[CH];
    __shared__ int    sh_task;
    __shared__ int    sh_last;
    __shared__ int    sh_k;

    const int t    = threadIdx.x;
    const int lane = t & 31;
    const int warp = t >> 5;
    const int q    = t & 7;

    for (;;) {
        __syncthreads();                       // protect shared vars from prev iter
        if (t == 0) sh_task = (int)atomicAdd(&g_ctr, 1u);
        __syncthreads();
        const int task = sh_task;
        if (task >= TOTAL_TASKS) return;

        if (task < RED_TASKS) {
            // ---------------- reduction chunk ----------------
            const int b     = task / NCHUNK;
            const int chunk = task - b * NCHUNK;
            const unsigned base = ((unsigned)b * PIX + (unsigned)chunk * 1024u) * 8u;

            float4 s = make_float4(0.f, 0.f, 0.f, 0.f);
#pragma unroll 4
            for (int it = 0; it < 32; ++it) {
                unsigned pix = (unsigned)(it * 32 + (t >> 3));
                float4 v = __ldg(&x[base + pix * 8u + q]);
                s.x += v.x; s.y += v.y; s.z += v.z; s.w += v.w;
            }
#pragma unroll
            for (int off = 8; off <= 16; off <<= 1) {
                s.x += __shfl_xor_sync(0xffffffffu, s.x, off);
                s.y += __shfl_xor_sync(0xffffffffu, s.y, off);
                s.z += __shfl_xor_sync(0xffffffffu, s.z, off);
                s.w += __shfl_xor_sync(0xffffffffu, s.w, off);
            }
            if (lane < 8) sm[warp][lane] = s;
            __syncthreads();

            if (t < 8) {
                float4 acc = sm[0][t];
#pragma unroll
                for (int w = 1; w < 8; ++w) {
                    float4 v = sm[w][t];
                    acc.x += v.x; acc.y += v.y; acc.z += v.z; acc.w += v.w;
                }
                g_partial[(b * NCHUNK + chunk) * 8 + t] = acc;
                __threadfence();               // publish partials (writer-side fence)
            }
            __syncthreads();

            if (t == 0) {
                int old = atomicAdd(&g_done[b], 1);
                sh_last = (old == NCHUNK - 1);
            }
            __syncthreads();

            if (sh_last) {
                // last finisher for batch b: compute k[b]
                if (t == 0) __threadfence();   // acquire side
                __syncthreads();
                if (t < CH) {
                    const int qq = t >> 2, r = t & 3;
                    float ssum = 0.f;
                    for (int ch = 0; ch < NCHUNK; ++ch) {
                        float4 v = g_partial[(b * NCHUNK + ch) * 8 + qq];
                        ssum += (r == 0) ? v.x : (r == 1) ? v.y : (r == 2) ? v.z : v.w;
                    }
                    meanv[t] = ssum * (1.0f / (float)PIX);
                }
                __syncthreads();
                if (t == 0) {
                    float best = -3.402823466e38f;
                    int bi = 0;
#pragma unroll
                    for (int o = 0; o < 4; ++o) {
                        float l = __ldg(&b_cls[o]);
#pragma unroll
                        for (int cc = 0; cc < CH; ++cc)
                            l += meanv[cc] * __ldg(&W_cls[cc * 4 + o]);
                        if (l > best) { best = l; bi = o; }  // first-max (jnp.argmax)
                    }
                    g_k[b] = bi;
                    __threadfence();
                    atomicExch(&g_flag[b], 1);
                }
            }
        } else {
            // ---------------- rotation slice ----------------
            const int r     = task - RED_TASKS;
            const int b     = r / NCHUNK;
            const int slice = r - b * NCHUNK;

            if (t == 0) {
                while (0 == *(volatile int*)&g_flag[b]) __nanosleep(100);
                __threadfence();
                sh_k = g_k[b];
            }
            __syncthreads();
            const int k = sh_k;

            const float4* src_base = x   + (unsigned)b * PIX * 8u;
            float4*       out_base = out + (unsigned)b * PIX * 8u;

#pragma unroll 4
            for (int it = 0; it < 32; ++it) {
                int l   = it * 256 + t;
                int pix = slice * 1024 + (l >> 3);
                int j   = pix % HW;
                int i   = pix / HW;
                int si, sj;
                switch (k) {
                    case 0:  si = i;           sj = j;           break;
                    case 1:  si = j;           sj = HW - 1 - i;  break;
                    case 2:  si = HW - 1 - i;  sj = HW - 1 - j;  break;
                    default: si = HW - 1 - j;  sj = i;           break;
                }
                float4 v = __ldcs(&src_base[(unsigned)(si * HW + sj) * 8u + (unsigned)q]);
                __stcs(&out_base[(unsigned)pix * 8u + (unsigned)q], v);
            }
        }
    }
}

extern "C" void kernel_launch(void* const* d_in, const int* in_sizes, int n_in,
                              void* d_out, int out_size) {
    const float4* x     = (const float4*)d_in[0];
    const float*  W_cls = (const float*)d_in[1];
    const float*  b_cls = (const float*)d_in[2];
    float4*       out   = (float4*)d_out;

    init_kernel<<<1, 128>>>();
    fused_kernel<<<GRID_BLOCKS, 256>>>(x, W_cls, b_cls, out);
}

// round 4
// speedup vs baseline: 1.1432x; 1.0787x over previous
#include <cuda_runtime.h>
#include <cuda_bf16.h>

// Problem: x [64,224,224,32] f32; W_cls [32,4]; b_cls [4].
// out[b] = rot90(x[b], k[b]) with k[b] = argmax(mean_hw(x[b]) @ W + b).
//
// Persistent fused kernel, atomic work queue of 6272 tasks in 128 groups
// of 49. Group schedule interleaves reduce and rotate batches with a
// 12-batch delay so pure-read and read+write streams blend all run long:
//   g in [0,12):    reduce batch g
//   g in [12,116):  even -> reduce batch 12+(g-12)/2 ; odd -> rotate batch (g-12)/2
//   g in [116,128): rotate batch 52+(g-116)

#define BATCH 64
#define HW    224
#define PIX   (HW * HW)        // 50176
#define CH    32
#define NCHUNK 49
#define TOTAL_TASKS (2 * BATCH * NCHUNK)      // 6272
#define GRID_BLOCKS (148 * 8)

__device__ float4   g_partial[BATCH * NCHUNK * 8];
__device__ int      g_k[BATCH];
__device__ unsigned g_ctr;
__device__ int      g_done[BATCH];
__device__ int      g_flag[BATCH];

// per-k affine coefficients for src offset (in float4 units, before +q):
// src_off(i,j) = (si*HW + sj)*8 ;  si,sj affine in (i,j)
//   k=0: si=i,     sj=j      -> A=(1*HW+0)*8,  B=(0*HW+1)*8,  C=0
//   k=1: si=j,     sj=223-i  -> A=(0*HW-1)*8,  B=(1*HW+0)*8,  C=223*8
//   k=2: si=223-i, sj=223-j  -> A=-HW*8,       B=-8,          C=(223*HW+223)*8
//   k=3: si=223-j, sj=i      -> A=8,           B=-HW*8,       C=223*HW*8
__constant__ int c_A[4] = { HW*8,      -8,      -HW*8,   8      };
__constant__ int c_B[4] = { 8,          HW*8,   -8,      -HW*8  };
__constant__ int c_C[4] = { 0,          223*8,  (223*HW+223)*8, 223*HW*8 };

__global__ void init_kernel() {
    int t = threadIdx.x;
    if (t == 0) g_ctr = 0u;
    if (t < BATCH) { g_done[t] = 0; g_flag[t] = 0; }
}

__global__ void __launch_bounds__(256, 8) fused_kernel(const float4* __restrict__ x,
                                                       const float*  __restrict__ W_cls,
                                                       const float*  __restrict__ b_cls,
                                                       float4*       __restrict__ out) {
    __shared__ float4 sm[8][8];
    __shared__ float  meanv[CH];
    __shared__ int    sh_task;
    __shared__ int    sh_last;
    __shared__ int    sh_k;

    const int t    = threadIdx.x;
    const int lane = t & 31;
    const int warp = t >> 5;
    const int q    = t & 7;

    for (;;) {
        __syncthreads();
        if (t == 0) sh_task = (int)atomicAdd(&g_ctr, 1u);
        __syncthreads();
        const int task = sh_task;
        if (task >= TOTAL_TASKS) return;

        // -------- decode interleaved schedule --------
        const int g     = task / NCHUNK;
        const int slice = task - g * NCHUNK;
        int is_reduce, b;
        if (g < 12)        { is_reduce = 1; b = g; }
        else if (g < 116)  { int h = g - 12;
                             is_reduce = !(h & 1);
                             b = is_reduce ? (12 + (h >> 1)) : (h >> 1); }
        else               { is_reduce = 0; b = 52 + (g - 116); }

        if (is_reduce) {
            // ---------------- reduction chunk (order-identical to R1) -------
            const unsigned base = ((unsigned)b * PIX + (unsigned)slice * 1024u) * 8u;

            float4 s = make_float4(0.f, 0.f, 0.f, 0.f);
#pragma unroll 4
            for (int it = 0; it < 32; ++it) {
                unsigned pix = (unsigned)(it * 32 + (t >> 3));
                float4 v = __ldg(&x[base + pix * 8u + q]);
                s.x += v.x; s.y += v.y; s.z += v.z; s.w += v.w;
            }
#pragma unroll
            for (int off = 8; off <= 16; off <<= 1) {
                s.x += __shfl_xor_sync(0xffffffffu, s.x, off);
                s.y += __shfl_xor_sync(0xffffffffu, s.y, off);
                s.z += __shfl_xor_sync(0xffffffffu, s.z, off);
                s.w += __shfl_xor_sync(0xffffffffu, s.w, off);
            }
            if (lane < 8) sm[warp][lane] = s;
            __syncthreads();

            if (t < 8) {
                float4 acc = sm[0][t];
#pragma unroll
                for (int w = 1; w < 8; ++w) {
                    float4 v = sm[w][t];
                    acc.x += v.x; acc.y += v.y; acc.z += v.z; acc.w += v.w;
                }
                g_partial[(b * NCHUNK + slice) * 8 + t] = acc;
                __threadfence();
            }
            __syncthreads();

            if (t == 0) {
                int old = atomicAdd(&g_done[b], 1);
                sh_last = (old == NCHUNK - 1);
            }
            __syncthreads();

            if (sh_last) {
                if (t == 0) __threadfence();
                __syncthreads();
                if (t < CH) {
                    const int qq = t >> 2, r = t & 3;
                    float ssum = 0.f;
                    for (int ch = 0; ch < NCHUNK; ++ch) {
                        float4 v = g_partial[(b * NCHUNK + ch) * 8 + qq];
                        ssum += (r == 0) ? v.x : (r == 1) ? v.y : (r == 2) ? v.z : v.w;
                    }
                    meanv[t] = ssum * (1.0f / (float)PIX);
                }
                __syncthreads();
                if (t == 0) {
                    float best = -3.402823466e38f;
                    int bi = 0;
#pragma unroll
                    for (int o = 0; o < 4; ++o) {
                        float l = __ldg(&b_cls[o]);
#pragma unroll
                        for (int cc = 0; cc < CH; ++cc)
                            l += meanv[cc] * __ldg(&W_cls[cc * 4 + o]);
                        if (l > best) { best = l; bi = o; }  // first-max (jnp.argmax)
                    }
                    g_k[b] = bi;
                    __threadfence();
                    atomicExch(&g_flag[b], 1);
                }
            }
        } else {
            // ---------------- rotation slice (affine-incremental) ----------
            if (t == 0) {
                while (0 == *(volatile int*)&g_flag[b]) __nanosleep(100);
                __threadfence();
                sh_k = g_k[b];
            }
            __syncthreads();
            const int k = sh_k;
            const int A = c_A[k], Bc = c_B[k];

            const float4* src_base = x   + (unsigned)b * PIX * 8u;
            float4*       out_base = out + (unsigned)b * PIX * 8u;

            int pix0 = slice * 1024 + (t >> 3);
            int i = pix0 / HW;
            int j = pix0 - i * HW;
            int soff = A * i + Bc * j + c_C[k] + q;   // src float4 offset
            int doff = pix0 * 8 + q;                  // dst float4 offset
            const int stepB   = 32 * Bc;
            const int wrapAdj = A - HW * Bc;          // applied when j wraps

#pragma unroll 4
            for (int it = 0; it < 32; ++it) {
                float4 v = __ldcs(&src_base[soff]);
                __stcs(&out_base[doff], v);
                doff += 32 * 8;
                j += 32; soff += stepB;
                if (j >= HW) { j -= HW; soff += wrapAdj; }
            }
        }
    }
}

extern "C" void kernel_launch(void* const* d_in, const int* in_sizes, int n_in,
                              void* d_out, int out_size) {
    const float4* x     = (const float4*)d_in[0];
    const float*  W_cls = (const float*)d_in[1];
    const float*  b_cls = (const float*)d_in[2];
    float4*       out   = (float4*)d_out;

    init_kernel<<<1, 128>>>();
    fused_kernel<<<GRID_BLOCKS, 256>>>(x, W_cls, b_cls, out);
}

// round 5
// speedup vs baseline: 1.1513x; 1.0071x over previous
#include <cuda_runtime.h>
#include <cuda_bf16.h>

// Problem: x [64,224,224,32] f32; W_cls [32,4]; b_cls [4].
// out[b] = rot90(x[b], k[b]) with k[b] = argmax(mean_hw(x[b]) @ W + b).
//
// Persistent fused kernel, atomic work queue of 6272 tasks in 128 groups
// of 49, interleaved reduce/rotate with a D=6 batch delay. Rotate reads use
// normal caching so they HIT the L2 lines installed by the reduce pass of
// the same batch (x[b] = 6.4 MB, L2 = 126 MB, ~38 MB intervening fill).
//   g in [0,6):     reduce batch g
//   g in [6,122):   even h=g-6 -> reduce 6+h/2 ; odd -> rotate h/2
//   g in [122,128): rotate batch 58+(g-122)

#define BATCH 64
#define HW    224
#define PIX   (HW * HW)        // 50176
#define CH    32
#define NCHUNK 49
#define DLY   6
#define TOTAL_TASKS (2 * BATCH * NCHUNK)      // 6272
#define GRID_BLOCKS (148 * 8)

__device__ float4   g_partial[BATCH * NCHUNK * 8];
__device__ int      g_k[BATCH];
__device__ unsigned g_ctr;
__device__ int      g_done[BATCH];
__device__ int      g_flag[BATCH];

// per-k affine coefficients for src offset (float4 units, before +q):
//   k=0: si=i,     sj=j      k=1: si=j,     sj=223-i
//   k=2: si=223-i, sj=223-j  k=3: si=223-j, sj=i
__constant__ int c_A[4] = { HW*8,      -8,      -HW*8,   8      };
__constant__ int c_B[4] = { 8,          HW*8,   -8,      -HW*8  };
__constant__ int c_C[4] = { 0,          223*8,  (223*HW+223)*8, 223*HW*8 };

__global__ void init_kernel() {
    int t = threadIdx.x;
    if (t == 0) g_ctr = 0u;
    if (t < BATCH) { g_done[t] = 0; g_flag[t] = 0; }
}

__global__ void __launch_bounds__(256, 8) fused_kernel(const float4* __restrict__ x,
                                                       const float*  __restrict__ W_cls,
                                                       const float*  __restrict__ b_cls,
                                                       float4*       __restrict__ out) {
    __shared__ float4 sm[8][8];
    __shared__ float  meanv[CH];
    __shared__ int    sh_task;
    __shared__ int    sh_last;
    __shared__ int    sh_k;

    const int t    = threadIdx.x;
    const int lane = t & 31;
    const int warp = t >> 5;
    const int q    = t & 7;

    for (;;) {
        __syncthreads();
        if (t == 0) sh_task = (int)atomicAdd(&g_ctr, 1u);
        __syncthreads();
        const int task = sh_task;
        if (task >= TOTAL_TASKS) return;

        // -------- decode interleaved schedule (delay = DLY batches) --------
        const int g     = task / NCHUNK;
        const int slice = task - g * NCHUNK;
        int is_reduce, b;
        if (g < DLY)             { is_reduce = 1; b = g; }
        else if (g < 128 - DLY)  { int h = g - DLY;
                                   is_reduce = !(h & 1);
                                   b = is_reduce ? (DLY + (h >> 1)) : (h >> 1); }
        else                     { is_reduce = 0; b = (64 - DLY) + (g - (128 - DLY)); }

        if (is_reduce) {
            // ---------------- reduction chunk (order-identical to R1) -------
            const unsigned base = ((unsigned)b * PIX + (unsigned)slice * 1024u) * 8u;

            float4 s = make_float4(0.f, 0.f, 0.f, 0.f);
#pragma unroll 4
            for (int it = 0; it < 32; ++it) {
                unsigned pix = (unsigned)(it * 32 + (t >> 3));
                float4 v = __ldg(&x[base + pix * 8u + q]);
                s.x += v.x; s.y += v.y; s.z += v.z; s.w += v.w;
            }
#pragma unroll
            for (int off = 8; off <= 16; off <<= 1) {
                s.x += __shfl_xor_sync(0xffffffffu, s.x, off);
                s.y += __shfl_xor_sync(0xffffffffu, s.y, off);
                s.z += __shfl_xor_sync(0xffffffffu, s.z, off);
                s.w += __shfl_xor_sync(0xffffffffu, s.w, off);
            }
            if (lane < 8) sm[warp][lane] = s;
            __syncthreads();

            if (t < 8) {
                float4 acc = sm[0][t];
#pragma unroll
                for (int w = 1; w < 8; ++w) {
                    float4 v = sm[w][t];
                    acc.x += v.x; acc.y += v.y; acc.z += v.z; acc.w += v.w;
                }
                g_partial[(b * NCHUNK + slice) * 8 + t] = acc;
                __threadfence();
            }
            __syncthreads();

            if (t == 0) {
                int old = atomicAdd(&g_done[b], 1);
                sh_last = (old == NCHUNK - 1);
            }
            __syncthreads();

            if (sh_last) {
                if (t == 0) __threadfence();
                __syncthreads();
                if (t < CH) {
                    const int qq = t >> 2, r = t & 3;
                    float ssum = 0.f;
                    for (int ch = 0; ch < NCHUNK; ++ch) {
                        float4 v = g_partial[(b * NCHUNK + ch) * 8 + qq];
                        ssum += (r == 0) ? v.x : (r == 1) ? v.y : (r == 2) ? v.z : v.w;
                    }
                    meanv[t] = ssum * (1.0f / (float)PIX);
                }
                __syncthreads();
                if (t == 0) {
                    float best = -3.402823466e38f;
                    int bi = 0;
#pragma unroll
                    for (int o = 0; o < 4; ++o) {
                        float l = __ldg(&b_cls[o]);
#pragma unroll
                        for (int cc = 0; cc < CH; ++cc)
                            l += meanv[cc] * __ldg(&W_cls[cc * 4 + o]);
                        if (l > best) { best = l; bi = o; }  // first-max (jnp.argmax)
                    }
                    g_k[b] = bi;
                    __threadfence();
                    atomicExch(&g_flag[b], 1);
                }
            }
        } else {
            // ---------------- rotation slice (affine-incremental) ----------
            if (t == 0) {
                while (0 == *(volatile int*)&g_flag[b]) __nanosleep(100);
                __threadfence();
                sh_k = g_k[b];
            }
            __syncthreads();
            const int k = sh_k;
            const int A = c_A[k], Bc = c_B[k];

            const float4* src_base = x   + (unsigned)b * PIX * 8u;
            float4*       out_base = out + (unsigned)b * PIX * 8u;

            int pix0 = slice * 1024 + (t >> 3);
            int i = pix0 / HW;
            int j = pix0 - i * HW;
            int soff = A * i + Bc * j + c_C[k] + q;   // src float4 offset
            int doff = pix0 * 8 + q;                  // dst float4 offset
            const int stepB   = 32 * Bc;
            const int wrapAdj = A - HW * Bc;

#pragma unroll 4
            for (int it = 0; it < 32; ++it) {
                float4 v = __ldg(&src_base[soff]);    // normal caching: L2 reuse
                __stcs(&out_base[doff], v);           // streaming store: no pollution
                doff += 32 * 8;
                j += 32; soff += stepB;
                if (j >= HW) { j -= HW; soff += wrapAdj; }
            }
        }
    }
}

extern "C" void kernel_launch(void* const* d_in, const int* in_sizes, int n_in,
                              void* d_out, int out_size) {
    const float4* x     = (const float4*)d_in[0];
    const float*  W_cls = (const float*)d_in[1];
    const float*  b_cls = (const float*)d_in[2];
    float4*       out   = (float4*)d_out;

    init_kernel<<<1, 128>>>();
    fused_kernel<<<GRID_BLOCKS, 256>>>(x, W_cls, b_cls, out);
}